// round 6
// baseline (speedup 1.0000x reference)
#include <cuda_runtime.h>
#include <cuda_bf16.h>
#include <cstdint>

// Problem constants
#define BB    32
#define CIN   64
#define COUT  64
#define NN    4096
#define MODES 1024
#define KOUT  2049   // N/2 + 1

// Scratch (device globals — no allocation allowed)
__device__ float g_xht[BB * CIN * MODES];        // truncated "FHT" output, [b*64+i][k]
__device__ float g_mix[BB * CIN * MODES];        // batch/channel-mixed operand g[b,i,k]
__device__ float g_yht[BB * COUT * MODES];       // spectral product, [b*64+o][k]
__device__ float g_cas[MODES * KOUT];            // cas(2*pi*k*n/2049), [k][n]

// ---------------------------------------------------------------------------
// Kernel 1: per-row length-4096 "cas-FFT" matching recursive_fht exactly.
// Iterative radix-2 DIT with bit-reversed input; real twiddle cas(2*pi*j/s);
// butterfly (a + t*b, a - t*b). Keep only first 1024 outputs.
// ---------------------------------------------------------------------------
__global__ __launch_bounds__(512) void fht_kernel(const float* __restrict__ x) {
    __shared__ float s[NN];
    const int row = blockIdx.x;              // row = b*64 + i, 2048 rows
    const float* xr = x + (size_t)row * NN;

    // bit-reversed load (12-bit reverse)
    for (int n = threadIdx.x; n < NN; n += 512) {
        int p = __brev((unsigned)n) >> 20;
        s[p] = xr[n];
    }
    __syncthreads();

    #pragma unroll 1
    for (int lh = 0; lh < 12; lh++) {
        const int half = 1 << lh;
        const float astep = 6.28318530717958647692f / (float)(2 << lh);
        for (int m = threadIdx.x; m < (NN >> 1); m += 512) {
            const int j  = m & (half - 1);
            const int i0 = ((m >> lh) << (lh + 1)) + j;
            const int i1 = i0 + half;
            float sn, cs;
            __sincosf((float)j * astep, &sn, &cs);
            const float t = cs + sn;
            const float a = s[i0];
            const float b = s[i1];
            s[i0] = fmaf(t, b, a);
            s[i1] = fmaf(-t, b, a);
        }
        __syncthreads();
    }

    float* outr = g_xht + (size_t)row * MODES;
    for (int k = threadIdx.x; k < MODES; k += 512)
        outr[k] = s[k];
}

// ---------------------------------------------------------------------------
// Kernel 2: elementwise mixing implementing the batch-flip / channel-flip
// algebra of compl_mul1d:
//   g[b,i,k] = 0.5*(X[b,i,k] + X[b,63-i,k] + X[31-b,i,k] - X[31-b,63-i,k])
// ---------------------------------------------------------------------------
__global__ __launch_bounds__(256) void mix_kernel() {
    const int idx = blockIdx.x * 256 + threadIdx.x;
    if (idx >= BB * CIN * MODES) return;
    const int k = idx & (MODES - 1);
    const int r = idx >> 10;
    const int i = r & 63;
    const int b = r >> 6;
    const int ii = 63 - i;
    const int bb = 31 - b;
    const float v0 = g_xht[(((size_t)b * 64 + i)  << 10) + k];
    const float v1 = g_xht[(((size_t)b * 64 + ii) << 10) + k];
    const float v2 = g_xht[(((size_t)bb * 64 + i) << 10) + k];
    const float v3 = g_xht[(((size_t)bb * 64 + ii)<< 10) + k];
    g_mix[idx] = 0.5f * (v0 + v1 + v2 - v3);
}

// ---------------------------------------------------------------------------
// Kernel 3: per-k batched GEMM  y[b,o,k] = sum_i g[b,i,k] * w[i,o,k]
// blockDim (32 k-lanes, 8 o), grid (32 k-tiles, 8 o-tiles).
// Each thread: fixed (k,o), accumulators over all 32 b.
// ---------------------------------------------------------------------------
__global__ __launch_bounds__(256) void specmul_kernel(const float* __restrict__ w) {
    __shared__ float xs[32][33];
    const int tx = threadIdx.x;            // k within tile
    const int ty = threadIdx.y;            // o within tile
    const int k  = blockIdx.x * 32 + tx;
    const int o  = blockIdx.y * 8 + ty;

    float acc[32];
    #pragma unroll
    for (int b = 0; b < 32; b++) acc[b] = 0.0f;

    for (int i = 0; i < CIN; i++) {
        __syncthreads();
        #pragma unroll
        for (int s4 = 0; s4 < 4; s4++) {
            const int b = ty + s4 * 8;
            xs[b][tx] = g_mix[(((size_t)b * 64 + i) << 10) + k];
        }
        __syncthreads();
        const float wv = w[(((size_t)i * 64 + o) << 10) + k];
        #pragma unroll
        for (int b = 0; b < 32; b++)
            acc[b] = fmaf(xs[b][tx], wv, acc[b]);
    }

    #pragma unroll
    for (int b = 0; b < 32; b++)
        g_yht[(((size_t)b * 64 + o) << 10) + k] = acc[b];
}

// ---------------------------------------------------------------------------
// Kernel 4: cas table  C[k][n] = cos+sin(2*pi*(k*n mod 2049)/2049)
// ---------------------------------------------------------------------------
__global__ __launch_bounds__(256) void cas_kernel() {
    const int idx = blockIdx.x * 256 + threadIdx.x;
    if (idx >= MODES * KOUT) return;
    const int n = idx % KOUT;
    const int k = idx / KOUT;
    const int m = (int)(((long long)k * (long long)n) % KOUT);
    const float ang = 6.28318530717958647692f * (float)m / (float)KOUT;
    float sn, cs;
    sincosf(ang, &sn, &cs);
    g_cas[idx] = cs + sn;
}

// ---------------------------------------------------------------------------
// Kernel 5: idht GEMM  out[r,n] = (1/2049) * sum_k Y[r,k] * C[k,n]
// M=2048, N=2049, K=1024. 64x64 tile, BK=16, 256 threads, 4x4 microtile.
// ---------------------------------------------------------------------------
__global__ __launch_bounds__(256) void idht_gemm_kernel(float* __restrict__ out) {
    __shared__ __align__(16) float As[16][64];   // [k][m]
    __shared__ __align__(16) float Bs[16][64];   // [k][n]

    const int tid = threadIdx.x;
    const int m0 = blockIdx.y * 64;
    const int n0 = blockIdx.x * 64;
    const int tm = (tid >> 4) * 4;   // 0..60
    const int tn = (tid & 15) * 4;   // 0..60

    float acc[4][4] = {};

    const int ar = tid >> 2;           // 0..63
    const int ac = (tid & 3) << 2;     // 0,4,8,12
    const int br = tid >> 4;           // 0..15
    const int bc = (tid & 15) << 2;    // 0..60

    for (int kk = 0; kk < MODES; kk += 16) {
        // A tile (coalesced float4 along k), store transposed As[k][m]
        const float4 av = *(const float4*)&g_yht[(size_t)(m0 + ar) * MODES + kk + ac];
        As[ac + 0][ar] = av.x;
        As[ac + 1][ar] = av.y;
        As[ac + 2][ar] = av.z;
        As[ac + 3][ar] = av.w;
        // B tile (row stride 2049 is odd -> scalar guarded loads)
        #pragma unroll
        for (int t = 0; t < 4; t++) {
            const int n = n0 + bc + t;
            Bs[br][bc + t] = (n < KOUT) ? g_cas[(size_t)(kk + br) * KOUT + n] : 0.0f;
        }
        __syncthreads();

        #pragma unroll
        for (int ks = 0; ks < 16; ks++) {
            const float4 a4 = *(const float4*)&As[ks][tm];
            const float4 b4 = *(const float4*)&Bs[ks][tn];
            const float a[4] = {a4.x, a4.y, a4.z, a4.w};
            const float b[4] = {b4.x, b4.y, b4.z, b4.w};
            #pragma unroll
            for (int i = 0; i < 4; i++)
                #pragma unroll
                for (int j = 0; j < 4; j++)
                    acc[i][j] = fmaf(a[i], b[j], acc[i][j]);
        }
        __syncthreads();
    }

    const float inv = 1.0f / (float)KOUT;
    #pragma unroll
    for (int i = 0; i < 4; i++) {
        const int m = m0 + tm + i;
        #pragma unroll
        for (int j = 0; j < 4; j++) {
            const int n = n0 + tn + j;
            if (n < KOUT)
                out[(size_t)m * KOUT + n] = acc[i][j] * inv;
        }
    }
}

// ---------------------------------------------------------------------------
extern "C" void kernel_launch(void* const* d_in, const int* in_sizes, int n_in,
                              void* d_out, int out_size) {
    const float* x = (const float*)d_in[0];        // [32, 64, 4096]
    const float* w = (const float*)d_in[1];        // [64, 64, 1024]
    float* out = (float*)d_out;                    // [32, 64, 2049]
    (void)in_sizes; (void)n_in; (void)out_size;

    // Stage 1: truncated cas-FFT per (b, i) row
    fht_kernel<<<BB * CIN, 512>>>(x);

    // Stage 2: flip mixing
    {
        const int total = BB * CIN * MODES;
        mix_kernel<<<(total + 255) / 256, 256>>>();
    }

    // Stage 3: per-k spectral GEMM
    {
        dim3 blk(32, 8);
        dim3 grd(MODES / 32, COUT / 8);
        specmul_kernel<<<grd, blk>>>(w);
    }

    // Stage 4: cas table (independent of stages 1-3, but stream-ordered is fine)
    {
        const int total = MODES * KOUT;
        cas_kernel<<<(total + 255) / 256, 256>>>();
    }

    // Stage 5: idht GEMM
    {
        dim3 blk(256);
        dim3 grd((KOUT + 63) / 64, (BB * COUT) / 64);
        idht_gemm_kernel<<<grd, blk>>>(out);
    }
}

// round 10
// speedup vs baseline: 1.5955x; 1.5955x over previous
#include <cuda_runtime.h>
#include <cuda_bf16.h>
#include <cstdint>

// Problem constants
#define BB    32
#define CIN   64
#define COUT  64
#define NN    4096
#define MODES 1024
#define KOUT  2049   // N/2 + 1
#define NPAD  2176   // 17 * 128 (padded N for tensor-core tiling)

// Scratch (device globals — no allocation allowed). bf16 arrays force-aligned
// so cp.async.cg 16B global addresses are guaranteed legal.
__device__ float g_xht[BB * CIN * MODES];
__device__ float g_mix[BB * CIN * MODES];
__device__ float g_yht[BB * COUT * MODES];
__device__ __align__(256) __nv_bfloat16 g_yhi[BB * COUT * MODES];   // Y split-hi
__device__ __align__(256) __nv_bfloat16 g_ylo[BB * COUT * MODES];   // Y split-lo
__device__ __align__(256) __nv_bfloat16 g_chiT[NPAD * MODES];       // cas^T hi [n][k]
__device__ __align__(256) __nv_bfloat16 g_cloT[NPAD * MODES];       // cas^T lo

static __device__ __forceinline__ uint32_t smem_u32(const void* p) {
    uint32_t a;
    asm("{ .reg .u64 t; cvta.to.shared.u64 t, %1; cvt.u32.u64 %0, t; }"
        : "=r"(a) : "l"(p));
    return a;
}

#define CP_ASYNC_16(saddr, gaddr) \
    asm volatile("cp.async.cg.shared.global [%0], [%1], 16;" \
                 :: "r"(saddr), "l"(gaddr))
#define CP_ASYNC_COMMIT() asm volatile("cp.async.commit_group;" ::: "memory")
#define CP_ASYNC_WAIT2()  asm volatile("cp.async.wait_group 2;" ::: "memory")

#define LDMATRIX_X4(r0, r1, r2, r3, addr) \
    asm volatile("ldmatrix.sync.aligned.m8n8.x4.shared.b16 {%0,%1,%2,%3}, [%4];" \
                 : "=r"(r0), "=r"(r1), "=r"(r2), "=r"(r3) : "r"(addr))

#define MMA_BF16(c, a, b0, b1) \
    asm volatile("mma.sync.aligned.m16n8k16.row.col.f32.bf16.bf16.f32 " \
                 "{%0,%1,%2,%3}, {%4,%5,%6,%7}, {%8,%9}, {%0,%1,%2,%3};" \
                 : "+f"((c)[0]), "+f"((c)[1]), "+f"((c)[2]), "+f"((c)[3]) \
                 : "r"((a)[0]), "r"((a)[1]), "r"((a)[2]), "r"((a)[3]), \
                   "r"(b0), "r"(b1))

// ---------------------------------------------------------------------------
// Kernel 1: per-row length-4096 "cas-FFT" matching recursive_fht exactly.
// ---------------------------------------------------------------------------
__global__ __launch_bounds__(512) void fht_kernel(const float* __restrict__ x) {
    __shared__ float s[NN];
    const int row = blockIdx.x;
    const float* xr = x + (size_t)row * NN;

    for (int n = threadIdx.x; n < NN; n += 512) {
        int p = __brev((unsigned)n) >> 20;
        s[p] = xr[n];
    }
    __syncthreads();

    #pragma unroll 1
    for (int lh = 0; lh < 12; lh++) {
        const int half = 1 << lh;
        const float astep = 6.28318530717958647692f / (float)(2 << lh);
        for (int m = threadIdx.x; m < (NN >> 1); m += 512) {
            const int j  = m & (half - 1);
            const int i0 = ((m >> lh) << (lh + 1)) + j;
            const int i1 = i0 + half;
            float sn, cs;
            __sincosf((float)j * astep, &sn, &cs);
            const float t = cs + sn;
            const float a = s[i0];
            const float b = s[i1];
            s[i0] = fmaf(t, b, a);
            s[i1] = fmaf(-t, b, a);
        }
        __syncthreads();
    }

    float* outr = g_xht + (size_t)row * MODES;
    for (int k = threadIdx.x; k < MODES; k += 512)
        outr[k] = s[k];
}

// ---------------------------------------------------------------------------
// Kernel 2: flip mixing  g[b,i,k] = 0.5*(X[b,i,k]+X[b,63-i,k]+X[31-b,i,k]-X[31-b,63-i,k])
// ---------------------------------------------------------------------------
__global__ __launch_bounds__(256) void mix_kernel() {
    const int idx = blockIdx.x * 256 + threadIdx.x;
    if (idx >= BB * CIN * MODES) return;
    const int k = idx & (MODES - 1);
    const int r = idx >> 10;
    const int i = r & 63;
    const int b = r >> 6;
    const int ii = 63 - i;
    const int bb = 31 - b;
    const float v0 = g_xht[(((size_t)b  * 64 + i ) << 10) + k];
    const float v1 = g_xht[(((size_t)b  * 64 + ii) << 10) + k];
    const float v2 = g_xht[(((size_t)bb * 64 + i ) << 10) + k];
    const float v3 = g_xht[(((size_t)bb * 64 + ii) << 10) + k];
    g_mix[idx] = 0.5f * (v0 + v1 + v2 - v3);
}

// ---------------------------------------------------------------------------
// Kernel 3: per-k spectral GEMM  y[b,o,k] = sum_i g[b,i,k] * w[i,o,k]
// ---------------------------------------------------------------------------
__global__ __launch_bounds__(256) void specmul_kernel(const float* __restrict__ w) {
    __shared__ float xs[32][33];
    const int tx = threadIdx.x;
    const int ty = threadIdx.y;
    const int k  = blockIdx.x * 32 + tx;
    const int o  = blockIdx.y * 8 + ty;

    float acc[32];
    #pragma unroll
    for (int b = 0; b < 32; b++) acc[b] = 0.0f;

    for (int i = 0; i < CIN; i++) {
        __syncthreads();
        #pragma unroll
        for (int s4 = 0; s4 < 4; s4++) {
            const int b = ty + s4 * 8;
            xs[b][tx] = g_mix[(((size_t)b * 64 + i) << 10) + k];
        }
        __syncthreads();
        const float wv = w[(((size_t)i * 64 + o) << 10) + k];
        #pragma unroll
        for (int b = 0; b < 32; b++)
            acc[b] = fmaf(xs[b][tx], wv, acc[b]);
    }

    #pragma unroll
    for (int b = 0; b < 32; b++)
        g_yht[(((size_t)b * 64 + o) << 10) + k] = acc[b];
}

// ---------------------------------------------------------------------------
// Kernel 4a: split Y into bf16 hi/lo
// ---------------------------------------------------------------------------
__global__ __launch_bounds__(256) void split_y_kernel() {
    const int idx = blockIdx.x * 256 + threadIdx.x;
    if (idx >= BB * COUT * MODES) return;
    const float v = g_yht[idx];
    const __nv_bfloat16 h = __float2bfloat16(v);
    g_yhi[idx] = h;
    g_ylo[idx] = __float2bfloat16(v - __bfloat162float(h));
}

// ---------------------------------------------------------------------------
// Kernel 4b: transposed cas table, split bf16 hi/lo.
// ---------------------------------------------------------------------------
__global__ __launch_bounds__(256) void cas_split_kernel() {
    const int idx = blockIdx.x * 256 + threadIdx.x;
    if (idx >= NPAD * MODES) return;
    const int k = idx & (MODES - 1);
    const int n = idx >> 10;
    if (n >= KOUT) {
        g_chiT[idx] = __float2bfloat16(0.0f);
        g_cloT[idx] = __float2bfloat16(0.0f);
        return;
    }
    const int m = (k * n) % KOUT;   // k*n < 2^31, exact
    const float ang = 6.28318530717958647692f * (float)m / (float)KOUT;
    float sn, cs;
    sincosf(ang, &sn, &cs);
    const float v = cs + sn;
    const __nv_bfloat16 h = __float2bfloat16(v);
    g_chiT[idx] = h;
    g_cloT[idx] = __float2bfloat16(v - __bfloat162float(h));
}

// ---------------------------------------------------------------------------
// Kernel 5: HMMA idht GEMM.
//   out[m][n] = (1/2049) * sum_k Y[m][k] * CT[n][k]
// Split-bf16: effective K = 3*1024 = 96 iters of BK=32,
// phases: (Yhi,Chi) kk<32, (Yhi,Clo) kk<64, (Ylo,Chi) kk<96.
// CTA 128x128, 8 warps (4m x 2n), warp tile 32x64, 3-stage cp.async pipeline.
// ---------------------------------------------------------------------------
#define BK        32
#define ROWPITCH  80                 // (32+8) halves * 2 bytes
#define STAGE_A   10240              // 128 * 80
#define STAGE_SZ  20480              // A + B
#define NSTAGE    3
#define NKIT      96
#define SMEM_TOT  (NSTAGE * STAGE_SZ)

static __device__ __forceinline__ void issue_stage(
    uint32_t sbase, int stage, int m0, int n0, int kk, int tid) {
    const int phase = kk >> 5;
    const int kl = (kk & 31) * BK;
    const __nv_bfloat16* Asrc = (phase < 2) ? g_yhi : g_ylo;
    const __nv_bfloat16* Bsrc = (phase == 1) ? g_cloT : g_chiT;

    const int row = tid >> 1;             // 0..127
    const int c0  = (tid & 1) * 16;       // halves: 0 or 16

    const uint32_t sA = sbase + stage * STAGE_SZ;
    const uint32_t sB = sA + STAGE_A;

    const __nv_bfloat16* ga = Asrc + (size_t)(m0 + row) * MODES + kl + c0;
    const __nv_bfloat16* gb = Bsrc + (size_t)(n0 + row) * MODES + kl + c0;
    const uint32_t soff = (uint32_t)(row * ROWPITCH + c0 * 2);

    CP_ASYNC_16(sA + soff,      ga);
    CP_ASYNC_16(sA + soff + 16, ga + 8);
    CP_ASYNC_16(sB + soff,      gb);
    CP_ASYNC_16(sB + soff + 16, gb + 8);
}

__global__ __launch_bounds__(256) void idht_hmma_kernel(float* __restrict__ out) {
    extern __shared__ char smem[];
    const uint32_t sbase = smem_u32(smem);
    const int tid  = threadIdx.x;
    const int wid  = tid >> 5;
    const int lane = tid & 31;
    const int m0 = blockIdx.y * 128;
    const int n0 = blockIdx.x * 128;

    const int warp_m = (wid & 3) * 32;    // 0,32,64,96
    const int warp_n = (wid >> 2) * 64;   // 0,64

    float acc[2][8][4] = {};

    // ldmatrix lane offsets
    const int a_row = lane & 15;
    const int a_col = (lane >> 4) * 8;                      // halves
    const int b_row = ((lane >> 4) & 1) * 8 + (lane & 7);
    const int b_col = ((lane >> 3) & 1) * 8;                // halves

    // Prologue: fill 3 stages
    #pragma unroll
    for (int s = 0; s < NSTAGE; s++) {
        issue_stage(sbase, s, m0, n0, s, tid);
        CP_ASYNC_COMMIT();
    }

    for (int kk = 0; kk < NKIT; kk++) {
        const int stage = kk % NSTAGE;
        CP_ASYNC_WAIT2();
        __syncthreads();

        const uint32_t sA = sbase + stage * STAGE_SZ;
        const uint32_t sB = sA + STAGE_A;

        #pragma unroll
        for (int ks = 0; ks < 2; ks++) {
            uint32_t a[2][4];
            #pragma unroll
            for (int mt = 0; mt < 2; mt++) {
                const uint32_t addr = sA
                    + (uint32_t)(warp_m + mt * 16 + a_row) * ROWPITCH
                    + (uint32_t)(a_col + ks * 16) * 2;
                LDMATRIX_X4(a[mt][0], a[mt][1], a[mt][2], a[mt][3], addr);
            }
            uint32_t b[8][2];
            #pragma unroll
            for (int np = 0; np < 4; np++) {
                const uint32_t addr = sB
                    + (uint32_t)(warp_n + np * 16 + b_row) * ROWPITCH
                    + (uint32_t)(b_col + ks * 16) * 2;
                uint32_t r0, r1, r2, r3;
                LDMATRIX_X4(r0, r1, r2, r3, addr);
                b[np * 2][0] = r0; b[np * 2][1] = r1;
                b[np * 2 + 1][0] = r2; b[np * 2 + 1][1] = r3;
            }
            #pragma unroll
            for (int mt = 0; mt < 2; mt++)
                #pragma unroll
                for (int nt = 0; nt < 8; nt++)
                    MMA_BF16(acc[mt][nt], a[mt], b[nt][0], b[nt][1]);
        }
        __syncthreads();

        if (kk + NSTAGE < NKIT) {
            issue_stage(sbase, stage, m0, n0, kk + NSTAGE, tid);
        }
        CP_ASYNC_COMMIT();
    }

    // Epilogue — SCALAR stores only: out rows have stride 2049 floats, so
    // odd rows are only 4-byte aligned; float2 stores would trap (round-7 bug).
    const float inv = 1.0f / (float)KOUT;
    const int gid = lane >> 2;     // groupID 0..7
    const int tig = lane & 3;
    #pragma unroll
    for (int mt = 0; mt < 2; mt++) {
        #pragma unroll
        for (int rr = 0; rr < 2; rr++) {   // c0/c1 vs c2/c3 (row, row+8)
            const int m = m0 + warp_m + mt * 16 + gid + rr * 8;
            float* orow = out + (size_t)m * KOUT;
            #pragma unroll
            for (int nt = 0; nt < 8; nt++) {
                const int n = n0 + warp_n + nt * 8 + tig * 2;
                const float v0 = acc[mt][nt][rr * 2 + 0] * inv;
                const float v1 = acc[mt][nt][rr * 2 + 1] * inv;
                if (n < KOUT)     orow[n]     = v0;
                if (n + 1 < KOUT) orow[n + 1] = v1;
            }
        }
    }
}

// ---------------------------------------------------------------------------
extern "C" void kernel_launch(void* const* d_in, const int* in_sizes, int n_in,
                              void* d_out, int out_size) {
    const float* x = (const float*)d_in[0];        // [32, 64, 4096]
    const float* w = (const float*)d_in[1];        // [64, 64, 1024]
    float* out = (float*)d_out;                    // [32, 64, 2049]
    (void)in_sizes; (void)n_in; (void)out_size;

    // Stage 1: truncated cas-FFT per (b, i) row
    fht_kernel<<<BB * CIN, 512>>>(x);

    // Stage 2: flip mixing
    mix_kernel<<<(BB * CIN * MODES + 255) / 256, 256>>>();

    // Stage 3: per-k spectral GEMM
    {
        dim3 blk(32, 8);
        dim3 grd(MODES / 32, COUT / 8);
        specmul_kernel<<<grd, blk>>>(w);
    }

    // Stage 4: split operands to bf16 hi/lo (+ transposed cas table)
    split_y_kernel<<<(BB * COUT * MODES + 255) / 256, 256>>>();
    cas_split_kernel<<<(NPAD * MODES + 255) / 256, 256>>>();

    // Stage 5: tensor-core (HMMA) idht GEMM
    cudaFuncSetAttribute(idht_hmma_kernel,
                         cudaFuncAttributeMaxDynamicSharedMemorySize, SMEM_TOT);
    {
        dim3 grd(NPAD / 128, (BB * COUT) / 128);   // 17 x 16
        idht_hmma_kernel<<<grd, 256, SMEM_TOT>>>(out);
    }
}

// round 15
// speedup vs baseline: 1.7510x; 1.0974x over previous
#include <cuda_runtime.h>
#include <cuda_bf16.h>
#include <cstdint>

// Problem constants
#define BB    32
#define CIN   64
#define COUT  64
#define NN    4096
#define MODES 1024
#define KOUT  2049   // N/2 + 1
#define NPAD  2176   // 17 * 128

// Scratch (device globals — no allocation allowed)
__device__ float g_xht[BB * CIN * MODES];
__device__ float g_mix[BB * CIN * MODES];
__device__ float g_twid2[4096];                  // tw[half+j] = cas(pi*j/half)
__device__ float g_castab[KOUT];                 // cas(2*pi*m/2049)
__device__ __align__(256) __nv_bfloat16 g_yhi[BB * COUT * MODES];
__device__ __align__(256) __nv_bfloat16 g_ylo[BB * COUT * MODES];
__device__ __align__(256) __nv_bfloat16 g_chiT[NPAD * MODES];
__device__ __align__(256) __nv_bfloat16 g_cloT[NPAD * MODES];

static __device__ __forceinline__ uint32_t smem_u32(const void* p) {
    uint32_t a;
    asm("{ .reg .u64 t; cvta.to.shared.u64 t, %1; cvt.u32.u64 %0, t; }"
        : "=r"(a) : "l"(p));
    return a;
}

#define CP_ASYNC_16(saddr, gaddr) \
    asm volatile("cp.async.cg.shared.global [%0], [%1], 16;" \
                 :: "r"(saddr), "l"(gaddr))
#define CP_ASYNC_COMMIT() asm volatile("cp.async.commit_group;" ::: "memory")
#define CP_ASYNC_WAIT2()  asm volatile("cp.async.wait_group 2;" ::: "memory")

#define LDMATRIX_X4(r0, r1, r2, r3, addr) \
    asm volatile("ldmatrix.sync.aligned.m8n8.x4.shared.b16 {%0,%1,%2,%3}, [%4];" \
                 : "=r"(r0), "=r"(r1), "=r"(r2), "=r"(r3) : "r"(addr))

#define MMA_BF16(c, a, b0, b1) \
    asm volatile("mma.sync.aligned.m16n8k16.row.col.f32.bf16.bf16.f32 " \
                 "{%0,%1,%2,%3}, {%4,%5,%6,%7}, {%8,%9}, {%0,%1,%2,%3};" \
                 : "+f"((c)[0]), "+f"((c)[1]), "+f"((c)[2]), "+f"((c)[3]) \
                 : "r"((a)[0]), "r"((a)[1]), "r"((a)[2]), "r"((a)[3]), \
                   "r"(b0), "r"(b1))

// ---------------------------------------------------------------------------
// Kernel 0: prep tables.
//   g_twid2[half+j] = cas(2*pi*j/(2*half))  (FFT-layout twiddles, conflict-free)
//   g_castab[m]     = cas(2*pi*m/2049)
// ---------------------------------------------------------------------------
__global__ __launch_bounds__(256) void prep_kernel() {
    const int idx = blockIdx.x * 256 + threadIdx.x;
    if (idx < 4096) {
        float v = 1.0f;
        if (idx >= 1) {
            const int half = 1 << (31 - __clz(idx));
            const int j = idx - half;
            const float ang = 3.14159265358979323846f * (float)j / (float)half;
            float sn, cs;
            sincosf(ang, &sn, &cs);
            v = cs + sn;
        }
        g_twid2[idx] = v;
    }
    if (idx < KOUT) {
        const float ang = 6.28318530717958647692f * (float)idx / (float)KOUT;
        float sn, cs;
        sincosf(ang, &sn, &cs);
        g_castab[idx] = cs + sn;
    }
}

// ---------------------------------------------------------------------------
// Kernel 1: per-row length-4096 cas-FFT matching recursive_fht exactly.
// Padded smem (phys = p + p/64) kills the 32-way bit-reversal bank conflict;
// twiddles come from the precomputed table (no MUFU in the hot loop).
// ---------------------------------------------------------------------------
#define PHYS(i) ((i) + ((i) >> 6))

__global__ __launch_bounds__(512) void fht_kernel(const float* __restrict__ x) {
    __shared__ float s[NN + (NN >> 6)];
    __shared__ float tw[4096];
    const int row = blockIdx.x;
    const float* xr = x + (size_t)row * NN;

    for (int i = threadIdx.x; i < 4096; i += 512)
        tw[i] = g_twid2[i];
    for (int n = threadIdx.x; n < NN; n += 512) {
        const int p = __brev((unsigned)n) >> 20;
        s[PHYS(p)] = xr[n];
    }
    __syncthreads();

    #pragma unroll 1
    for (int lh = 0; lh < 12; lh++) {
        const int half = 1 << lh;
        for (int m = threadIdx.x; m < (NN >> 1); m += 512) {
            const int j  = m & (half - 1);
            const int i0 = ((m >> lh) << (lh + 1)) + j;
            const int i1 = i0 + half;
            const float t = tw[half + j];
            const float a = s[PHYS(i0)];
            const float b = s[PHYS(i1)];
            s[PHYS(i0)] = fmaf(t, b, a);
            s[PHYS(i1)] = fmaf(-t, b, a);
        }
        __syncthreads();
    }

    float* outr = g_xht + (size_t)row * MODES;
    for (int k = threadIdx.x; k < MODES; k += 512)
        outr[k] = s[PHYS(k)];
}

// ---------------------------------------------------------------------------
// Kernel 2: flip mixing  g[b,i,k] = 0.5*(X[b,i,k]+X[b,63-i,k]+X[31-b,i,k]-X[31-b,63-i,k])
// ---------------------------------------------------------------------------
__global__ __launch_bounds__(256) void mix_kernel() {
    const int idx = blockIdx.x * 256 + threadIdx.x;
    if (idx >= BB * CIN * MODES) return;
    const int k = idx & (MODES - 1);
    const int r = idx >> 10;
    const int i = r & 63;
    const int b = r >> 6;
    const int ii = 63 - i;
    const int bb = 31 - b;
    const float v0 = g_xht[(((size_t)b  * 64 + i ) << 10) + k];
    const float v1 = g_xht[(((size_t)b  * 64 + ii) << 10) + k];
    const float v2 = g_xht[(((size_t)bb * 64 + i ) << 10) + k];
    const float v3 = g_xht[(((size_t)bb * 64 + ii) << 10) + k];
    g_mix[idx] = 0.5f * (v0 + v1 + v2 - v3);
}

// ---------------------------------------------------------------------------
// Kernel 3: per-k spectral GEMM  y[b,o,k] = sum_i g[b,i,k] * w[i,o,k]
// Fused bf16 hi/lo split of the result (drops g_yht + split_y kernel).
// blockDim (32k, 16o), grid (32, 4) -> 128 blocks = one wave.
// ---------------------------------------------------------------------------
__global__ __launch_bounds__(512) void specmul_kernel(const float* __restrict__ w) {
    __shared__ float xs[32][33];
    const int tx = threadIdx.x;
    const int ty = threadIdx.y;           // 0..15
    const int k  = blockIdx.x * 32 + tx;
    const int o  = blockIdx.y * 16 + ty;

    float acc[32];
    #pragma unroll
    for (int b = 0; b < 32; b++) acc[b] = 0.0f;

    for (int i = 0; i < CIN; i++) {
        __syncthreads();
        #pragma unroll
        for (int s2 = 0; s2 < 2; s2++) {
            const int b = ty + s2 * 16;
            xs[b][tx] = g_mix[(((size_t)b * 64 + i) << 10) + k];
        }
        __syncthreads();
        const float wv = w[(((size_t)i * 64 + o) << 10) + k];
        #pragma unroll
        for (int b = 0; b < 32; b++)
            acc[b] = fmaf(xs[b][tx], wv, acc[b]);
    }

    #pragma unroll
    for (int b = 0; b < 32; b++) {
        const size_t idx = (((size_t)b * 64 + o) << 10) + k;
        const float v = acc[b];
        const __nv_bfloat16 h = __float2bfloat16(v);
        g_yhi[idx] = h;
        g_ylo[idx] = __float2bfloat16(v - __bfloat162float(h));
    }
}

// ---------------------------------------------------------------------------
// Kernel 4: transposed cas table, split bf16 hi/lo, via table lookup.
// (k*n) mod 2049 computed with 2^11 == -1 (mod 2049): p = hi*2^11+lo == lo-hi.
// ---------------------------------------------------------------------------
__global__ __launch_bounds__(256) void cas_split_kernel() {
    const int idx = blockIdx.x * 256 + threadIdx.x;
    if (idx >= NPAD * MODES) return;
    const int k = idx & (MODES - 1);
    const int n = idx >> 10;
    if (n >= KOUT) {
        g_chiT[idx] = __float2bfloat16(0.0f);
        g_cloT[idx] = __float2bfloat16(0.0f);
        return;
    }
    const int p = k * n;                  // <= 1023*2048 < 2^22, exact
    int m = (p & 2047) - (p >> 11);
    if (m < 0) m += KOUT;
    const float v = g_castab[m];
    const __nv_bfloat16 h = __float2bfloat16(v);
    g_chiT[idx] = h;
    g_cloT[idx] = __float2bfloat16(v - __bfloat162float(h));
}

// ---------------------------------------------------------------------------
// Kernel 5: HMMA idht GEMM.  out[m][n] = (1/2049) * sum_k Y[m][k] * CT[n][k]
// Split-bf16: K_eff = 3*1024 = 96 iters of BK=32.
// CTA 128x128, 8 warps (4m x 2n), 4-stage cp.async ring, ONE sync per iter.
// ---------------------------------------------------------------------------
#define BK        32
#define ROWPITCH  80                 // (32+8) halves * 2 bytes
#define STAGE_A   10240              // 128 * 80
#define STAGE_SZ  20480              // A + B
#define NSTAGE    4
#define NKIT      96
#define SMEM_TOT  (NSTAGE * STAGE_SZ)   // 81920

static __device__ __forceinline__ void issue_stage(
    uint32_t sbase, int stage, int m0, int n0, int kk, int tid) {
    const int phase = kk >> 5;
    const int kl = (kk & 31) * BK;
    const __nv_bfloat16* Asrc = (phase < 2) ? g_yhi : g_ylo;
    const __nv_bfloat16* Bsrc = (phase == 1) ? g_cloT : g_chiT;

    const int row = tid >> 1;             // 0..127
    const int c0  = (tid & 1) * 16;       // halves: 0 or 16

    const uint32_t sA = sbase + stage * STAGE_SZ;
    const uint32_t sB = sA + STAGE_A;

    const __nv_bfloat16* ga = Asrc + (size_t)(m0 + row) * MODES + kl + c0;
    const __nv_bfloat16* gb = Bsrc + (size_t)(n0 + row) * MODES + kl + c0;
    const uint32_t soff = (uint32_t)(row * ROWPITCH + c0 * 2);

    CP_ASYNC_16(sA + soff,      ga);
    CP_ASYNC_16(sA + soff + 16, ga + 8);
    CP_ASYNC_16(sB + soff,      gb);
    CP_ASYNC_16(sB + soff + 16, gb + 8);
}

__global__ __launch_bounds__(256, 2) void idht_hmma_kernel(float* __restrict__ out) {
    extern __shared__ char smem[];
    const uint32_t sbase = smem_u32(smem);
    const int tid  = threadIdx.x;
    const int wid  = tid >> 5;
    const int lane = tid & 31;
    const int m0 = blockIdx.y * 128;
    const int n0 = blockIdx.x * 128;

    const int warp_m = (wid & 3) * 32;    // 0,32,64,96
    const int warp_n = (wid >> 2) * 64;   // 0,64

    float acc[2][8][4] = {};

    const int a_row = lane & 15;
    const int a_col = (lane >> 4) * 8;                      // halves
    const int b_row = ((lane >> 4) & 1) * 8 + (lane & 7);
    const int b_col = ((lane >> 3) & 1) * 8;                // halves

    // Prologue: fill 3 of 4 stages
    #pragma unroll
    for (int s = 0; s < NSTAGE - 1; s++) {
        issue_stage(sbase, s, m0, n0, s, tid);
        CP_ASYNC_COMMIT();
    }

    for (int kk = 0; kk < NKIT; kk++) {
        const int stage = kk & (NSTAGE - 1);
        CP_ASYNC_WAIT2();                 // stage kk's group has landed
        __syncthreads();                  // all warps done computing kk-1

        // Issue kk+3 into slot (kk+3)&3 == (kk-1)&3 (freed by the sync above).
        if (kk + NSTAGE - 1 < NKIT)
            issue_stage(sbase, (kk + NSTAGE - 1) & (NSTAGE - 1),
                        m0, n0, kk + NSTAGE - 1, tid);
        CP_ASYNC_COMMIT();                // exactly one group per iter (may be empty)

        const uint32_t sA = sbase + stage * STAGE_SZ;
        const uint32_t sB = sA + STAGE_A;

        #pragma unroll
        for (int ks = 0; ks < 2; ks++) {
            uint32_t a[2][4];
            #pragma unroll
            for (int mt = 0; mt < 2; mt++) {
                const uint32_t addr = sA
                    + (uint32_t)(warp_m + mt * 16 + a_row) * ROWPITCH
                    + (uint32_t)(a_col + ks * 16) * 2;
                LDMATRIX_X4(a[mt][0], a[mt][1], a[mt][2], a[mt][3], addr);
            }
            uint32_t b[8][2];
            #pragma unroll
            for (int np = 0; np < 4; np++) {
                const uint32_t addr = sB
                    + (uint32_t)(warp_n + np * 16 + b_row) * ROWPITCH
                    + (uint32_t)(b_col + ks * 16) * 2;
                uint32_t r0, r1, r2, r3;
                LDMATRIX_X4(r0, r1, r2, r3, addr);
                b[np * 2][0] = r0; b[np * 2][1] = r1;
                b[np * 2 + 1][0] = r2; b[np * 2 + 1][1] = r3;
            }
            #pragma unroll
            for (int mt = 0; mt < 2; mt++)
                #pragma unroll
                for (int nt = 0; nt < 8; nt++)
                    MMA_BF16(acc[mt][nt], a[mt], b[nt][0], b[nt][1]);
        }
    }

    // Epilogue — SCALAR stores only (stride-2049 rows: odd rows are 4B-aligned).
    const float inv = 1.0f / (float)KOUT;
    const int gid = lane >> 2;
    const int tig = lane & 3;
    #pragma unroll
    for (int mt = 0; mt < 2; mt++) {
        #pragma unroll
        for (int rr = 0; rr < 2; rr++) {
            const int m = m0 + warp_m + mt * 16 + gid + rr * 8;
            float* orow = out + (size_t)m * KOUT;
            #pragma unroll
            for (int nt = 0; nt < 8; nt++) {
                const int n = n0 + warp_n + nt * 8 + tig * 2;
                const float v0 = acc[mt][nt][rr * 2 + 0] * inv;
                const float v1 = acc[mt][nt][rr * 2 + 1] * inv;
                if (n < KOUT)     orow[n]     = v0;
                if (n + 1 < KOUT) orow[n + 1] = v1;
            }
        }
    }
}

// ---------------------------------------------------------------------------
extern "C" void kernel_launch(void* const* d_in, const int* in_sizes, int n_in,
                              void* d_out, int out_size) {
    const float* x = (const float*)d_in[0];        // [32, 64, 4096]
    const float* w = (const float*)d_in[1];        // [64, 64, 1024]
    float* out = (float*)d_out;                    // [32, 64, 2049]
    (void)in_sizes; (void)n_in; (void)out_size;

    // Stage 0: twiddle + cas tables
    prep_kernel<<<16, 256>>>();

    // Stage 1: truncated cas-FFT per (b, i) row
    fht_kernel<<<BB * CIN, 512>>>(x);

    // Stage 2: flip mixing
    mix_kernel<<<(BB * CIN * MODES + 255) / 256, 256>>>();

    // Stage 3: per-k spectral GEMM with fused bf16 split
    {
        dim3 blk(32, 16);
        dim3 grd(MODES / 32, COUT / 16);   // 32 x 4 = 128 blocks (one wave)
        specmul_kernel<<<grd, blk>>>(w);
    }

    // Stage 4: transposed cas table split (table lookup, no sincos)
    cas_split_kernel<<<(NPAD * MODES + 255) / 256, 256>>>();

    // Stage 5: tensor-core (HMMA) idht GEMM
    cudaFuncSetAttribute(idht_hmma_kernel,
                         cudaFuncAttributeMaxDynamicSharedMemorySize, SMEM_TOT);
    {
        dim3 grd(NPAD / 128, (BB * COUT) / 128);   // 17 x 16
        idht_hmma_kernel<<<grd, 256, SMEM_TOT>>>(out);
    }
}